// round 16
// baseline (speedup 1.0000x reference)
#include <cuda_runtime.h>
#include <math.h>

// Problem constants
#define BB 4
#define HH 128
#define WW 128
#define CIN 64
#define DR 16
#define HW 16384          // 128*128
#define NIMG 64           // B*DR
#define NF 65             // rfft width bins
#define FSZ (NF*128)      // 8320 floats per transposed freq image [v][u]
#define HWH 4096          // 64*64 (wavelet half-res)

// ---------------- device scratch (static, allocation-free) ----------------
__device__ float g_Wc[CIN][48];                 // combined qkv->dim weights
__device__ float g_q [BB][DR][HW];
__device__ float g_k [BB][DR][HW];
__device__ float g_v [BB][DR][HW];
__device__ float g_qm[BB][DR][HW];
__device__ float g_km[BB][DR][HW];
__device__ float g_vm[BB][DR][HW];
// Fourier scratch, TRANSPOSED layout [img][v][u] (u contiguous)
__device__ float g_zrT [NIMG][FSZ];
__device__ float g_ziT [NIMG][FSZ];
__device__ float g_ampT[NIMG][FSZ];
__device__ float g_phT [NIMG][FSZ];
__device__ float g_aloT[NIMG][FSZ];
__device__ float g_ahiT[NIMG][FSZ];
__device__ float g_ampoT[NIMG][FSZ];
// Wavelet scratch
__device__ float g_y [BB][64][HWH];
__device__ float g_m1[BB][96][HWH];
__device__ float g_m2[BB][96][HWH];
// Small matrices
__device__ float g_Sp[BB][64][768];             // partial Grams
__device__ float g_Th[BB * 8][1024];            // per-(batch,head) epilogue matrices
__device__ float g_cs[128], g_sn[128];          // twiddles

__device__ __forceinline__ float geluf(float x) {
    return 0.5f * x * (1.0f + erff(x * 0.70710678118654752440f));
}

// ---------------- init: combined weights + twiddles (parallel) ----------------
__global__ void k_init(const float* __restrict__ Wq, const float* __restrict__ Wk,
                       const float* __restrict__ Wv, const float* __restrict__ Wr) {
    int t = threadIdx.x; // 128
    int bx = blockIdx.x; // 0..24
    if (bx == 24) {
        float th = 6.283185307179586f * (float)t / 128.0f;
        g_cs[t] = cosf(th);
        g_sn[t] = sinf(th);
        return;
    }
    int o = bx * 128 + t;            // 0..3071
    int i = o / 48, j = o % 48;
    const float* Wsel = (j < 16) ? Wq : (j < 32) ? Wk : Wv;
    int jj = j & 15;
    float acc = 0.f;
#pragma unroll 4
    for (int f = 0; f < 512; f++) acc += Wsel[i * 512 + f] * Wr[f * 16 + jj];
    g_Wc[i][j] = acc;
}

// ---------------- k-only projection (critical path: feeds Fourier) ----------------
__global__ void k_projk(const float* __restrict__ x) {
    __shared__ float sW[CIN * 16];
    int t = threadIdx.x; // 128
    for (int i = t; i < CIN * 16; i += 128) {
        int row = i >> 4, col = i & 15;
        sW[i] = g_Wc[row][16 + col];
    }
    __syncthreads();
    int gid = blockIdx.x * 128 + t;              // 0..65535
    int b = gid >> 14, n = gid & 16383;
    float xr[64];
    const float4* xp = (const float4*)(x + (size_t)gid * 64);
#pragma unroll
    for (int i = 0; i < 16; i++) {
        float4 f = xp[i];
        xr[4 * i] = f.x; xr[4 * i + 1] = f.y; xr[4 * i + 2] = f.z; xr[4 * i + 3] = f.w;
    }
    float acc[16];
#pragma unroll
    for (int j = 0; j < 16; j++) acc[j] = 0.f;
#pragma unroll
    for (int i = 0; i < 64; i++) {
        float xi = xr[i];
#pragma unroll
        for (int j = 0; j < 16; j++) acc[j] += xi * sW[i * 16 + j];
    }
#pragma unroll
    for (int j = 0; j < 16; j++) g_k[b][j][n] = acc[j];
}

// ---------------- q+v projection (side streams: feeds spatial + wavelet) ----------------
__global__ void k_projqv(const float* __restrict__ x) {
    __shared__ float sW[CIN * 32];
    int t = threadIdx.x; // 128
    for (int i = t; i < CIN * 32; i += 128) {
        int row = i >> 5, col = i & 31;
        sW[i] = g_Wc[row][(col < 16) ? col : (col + 16)];   // q cols 0-15, v cols 32-47
    }
    __syncthreads();
    int gid = blockIdx.x * 128 + t;              // 0..65535
    int b = gid >> 14, n = gid & 16383;
    float xr[64];
    const float4* xp = (const float4*)(x + (size_t)gid * 64);
#pragma unroll
    for (int i = 0; i < 16; i++) {
        float4 f = xp[i];
        xr[4 * i] = f.x; xr[4 * i + 1] = f.y; xr[4 * i + 2] = f.z; xr[4 * i + 3] = f.w;
    }
    float acc[32];
#pragma unroll
    for (int j = 0; j < 32; j++) acc[j] = 0.f;
#pragma unroll
    for (int i = 0; i < 64; i++) {
        float xi = xr[i];
#pragma unroll
        for (int j = 0; j < 32; j++) acc[j] += xi * sW[i * 32 + j];
    }
#pragma unroll
    for (int j = 0; j < 16; j++) {
        g_q[b][j][n] = acc[j];
        g_v[b][j][n] = acc[16 + j];
    }
}

// ---------------- Spatial unit (q path) — fused dw+gelu+pw ----------------
__global__ void k_spatial(const float* __restrict__ dw, const float* __restrict__ pw,
                          const float* __restrict__ gamma) {
    __shared__ float sin_[16][324];   // 18x18 halo tiles, 16 channels
    __shared__ float sdw[144], spw[256], sg[16];
    int t = threadIdx.x; // 256
    int b = blockIdx.x >> 6;
    int tile = blockIdx.x & 63;
    int i0 = (tile >> 3) * 16, j0 = (tile & 7) * 16;
    if (t < 144) sdw[t] = dw[t];
    spw[t] = pw[t];
    if (t < 16) sg[t] = gamma[t];
    for (int idx = t; idx < 16 * 324; idx += 256) {
        int c = idx / 324, rem = idx % 324;
        int ii = rem / 18, jj = rem % 18;
        int gi = i0 - 1 + ii, gj = j0 - 1 + jj;
        float v = 0.f;
        if (gi >= 0 && gi < 128 && gj >= 0 && gj < 128) v = g_q[b][c][gi * 128 + gj];
        sin_[c][rem] = v;
    }
    __syncthreads();
    int li = t >> 4, lj = t & 15;
    float m[16];
#pragma unroll
    for (int c = 0; c < 16; c++) {
        float acc = 0.f;
#pragma unroll
        for (int di = 0; di < 3; di++)
#pragma unroll
            for (int dj = 0; dj < 3; dj++)
                acc += sdw[c * 9 + di * 3 + dj] * sin_[c][(li + di) * 18 + (lj + dj)];
        m[c] = geluf(acc);
    }
    int pix = (i0 + li) * 128 + (j0 + lj);
#pragma unroll
    for (int c = 0; c < 16; c++) {
        float acc = 0.f;
#pragma unroll
        for (int ci = 0; ci < 16; ci++) acc += spw[c * 16 + ci] * m[ci];
        g_qm[b][c][pix] = sin_[c][(li + 1) * 18 + (lj + 1)] + sg[c] * acc;
    }
}

// ---------------- Fourier unit (k path): radix-2 split DFTs, twiddle recurrence ----------------
// fwd W: per block 4 rows; Z[v] = sum_{x<64} (row[x] +- row[x+64]) w^{xv}
__global__ void k_fwdW() {
    __shared__ float raw[512], rE[256], rO[256];
    int t = threadIdx.x; // 288
    int img = blockIdx.x >> 5;
    int y0 = (blockIdx.x & 31) * 4;
    const float* kflat = &g_k[0][0][0];
    for (int idx = t; idx < 512; idx += 288) {
        int r = idx >> 7, x = idx & 127;
        raw[idx] = kflat[img * HW + (y0 + r) * 128 + x];
    }
    __syncthreads();
    for (int idx = t; idx < 256; idx += 288) {
        int r = idx >> 6, x = idx & 63;
        float a = raw[r * 128 + x], bv = raw[r * 128 + 64 + x];
        rE[idx] = a + bv;
        rO[idx] = a - bv;
    }
    __syncthreads();
    if (t < 260) {
        int r = t / 65, v = t % 65;
        const float* rp = (v & 1) ? (rO + r * 64) : (rE + r * 64);
        float stx = g_cs[v & 127], sty = g_sn[v & 127];   // e^{+i vθ}
        float s2x = stx * stx - sty * sty;
        float s2y = 2.f * stx * sty;
        float wEx = 1.f, wEy = 0.f;        // angle 0
        float wOx = stx, wOy = sty;        // angle vθ
        float ar = 0.f, ai = 0.f;
#pragma unroll 8
        for (int x = 0; x < 64; x += 2) {
            float2 rv2 = *(const float2*)&rp[x];
            ar += rv2.x * wEx + rv2.y * wOx;
            ai -= rv2.x * wEy + rv2.y * wOy;
            float nEx = wEx * s2x - wEy * s2y;
            wEy = wEy * s2x + wEx * s2y; wEx = nEx;
            float nOx = wOx * s2x - wOy * s2y;
            wOy = wOy * s2x + wOx * s2y; wOx = nOx;
        }
        g_zrT[img][v * 128 + y0 + r] = ar;
        g_ziT[img][v * 128 + y0 + r] = ai;
    }
}

// fwd H + amp/phase: block = (img, 4 v-cols), 128 threads; twiddle recurrence.
// Parity-uniform warps: u = 2*(t&63) + (t>>6) — all lanes in a warp share zE2/zO2,
// so every inner-loop LDS.128 is a single-wavefront broadcast.
__global__ void k_fwdH() {
    __shared__ float2 zE2[256], zO2[256];   // (re, im), 4 cols x 64
    int t = threadIdx.x; // 128
    int img = blockIdx.x / 17;
    int vg = blockIdx.x % 17;
    int v0 = vg * 4;
    int cnt = (vg == 16) ? 1 : 4;
    for (int idx = t; idx < cnt * 64; idx += 128) {
        int vv = idx >> 6, yy = idx & 63;
        int base = (v0 + vv) * 128;
        float a0 = g_zrT[img][base + yy], a1 = g_zrT[img][base + 64 + yy];
        float b0 = g_ziT[img][base + yy], b1 = g_ziT[img][base + 64 + yy];
        zE2[idx] = make_float2(a0 + a1, b0 + b1);
        zO2[idx] = make_float2(a0 - a1, b0 - b1);
    }
    __syncthreads();
    int u = ((t & 63) << 1) | (t >> 6);     // warps 0-1: even u; warps 2-3: odd u
    const float2* zsel = (u & 1) ? zO2 : zE2;
    float stx = g_cs[u], sty = g_sn[u];        // e^{+i uθ}
    float s2x = stx * stx - sty * sty;
    float s2y = 2.f * stx * sty;
    float wEx = 1.f, wEy = 0.f;                // angle 0 (yy even chain)
    float wOx = stx, wOy = sty;                // angle uθ (yy odd chain)
    float xr[4], xi[4];
#pragma unroll
    for (int q = 0; q < 4; q++) { xr[q] = 0.f; xi[q] = 0.f; }
#pragma unroll 4
    for (int yy = 0; yy < 64; yy += 2) {
#pragma unroll
        for (int q = 0; q < 4; q++) {
            if (q < cnt) {
                float4 z2 = *(const float4*)&zsel[q * 64 + yy];
                xr[q] += wEx * z2.x + wEy * z2.y + wOx * z2.z + wOy * z2.w;
                xi[q] += wEx * z2.y - wEy * z2.x + wOx * z2.w - wOy * z2.z;
            }
        }
        float nEx = wEx * s2x - wEy * s2y;
        wEy = wEy * s2x + wEx * s2y; wEx = nEx;
        float nOx = wOx * s2x - wOy * s2y;
        wOy = wOy * s2x + wOx * s2y; wOx = nOx;
    }
#pragma unroll
    for (int q = 0; q < 4; q++) {
        if (q < cnt) {
            float a = xr[q] * (1.0f / 128.0f), bq = xi[q] * (1.0f / 128.0f);
            int o = (v0 + q) * 128 + u;
            g_ampT[img][o] = sqrtf(a * a + bq * bq);
            g_phT[img][o]  = atan2f(bq, a);
        }
    }
}

// pointwise freq-domain convs (transposed layout)
__global__ void k_pwf(const float* __restrict__ alpw, const float* __restrict__ ahpw,
                      const float* __restrict__ phpw, const float* __restrict__ phs) {
    __shared__ float wl[256], wh[256], wp[256];
    int t = threadIdx.x; // 256
    wl[t] = alpw[t]; wh[t] = ahpw[t]; wp[t] = phpw[t];
    __syncthreads();
    int gid = blockIdx.x * 256 + t;          // < BB*FSZ = 33280
    int b = gid / FSZ;
    int rem = gid - b * FSZ;
    int v = rem >> 7, u = rem & 127;
    float a[16], p[16];
#pragma unroll
    for (int c = 0; c < 16; c++) { a[c] = g_ampT[b * 16 + c][rem]; p[c] = g_phT[b * 16 + c][rem]; }
    float yy = (float)u * (1.0f / 127.0f);
    float xx = (float)v * (1.0f / 64.0f);
    float rr = sqrtf(yy * yy + xx * xx);
    float low = 1.0f / (1.0f + __expf(-(0.25f - rr) * 20.0f));
    float high = 1.0f - low;
    float ps = phs[0];
#pragma unroll
    for (int c = 0; c < 16; c++) {
        float s1 = 0.f, s2 = 0.f, s3 = 0.f;
#pragma unroll
        for (int ci = 0; ci < 16; ci++) {
            s1 += wl[c * 16 + ci] * a[ci];
            s2 += wh[c * 16 + ci] * a[ci];
            s3 += wp[c * 16 + ci] * p[ci];
        }
        g_aloT[b * 16 + c][rem] = geluf(s1 * low);
        g_ahiT[b * 16 + c][rem] = geluf(s2 * high);
        g_phT [b * 16 + c][rem] = p[c] + ps * s3;
    }
}

__global__ void k_dwf(const float* __restrict__ aldw, const float* __restrict__ ahdw) {
    int gid = blockIdx.x * 256 + threadIdx.x;   // < NIMG*FSZ = 532480
    int img = gid / FSZ;
    int rem = gid - img * FSZ;
    int v = rem >> 7, u = rem & 127;
    int c = img & 15;
    const float* wl = aldw + c * 9;
    const float* wh = ahdw + c * 9;
    float acc = 0.f;
#pragma unroll
    for (int du = -1; du <= 1; du++)
#pragma unroll
        for (int dv = -1; dv <= 1; dv++) {
            int uu = u + du, vv = v + dv;
            if (uu >= 0 && uu < 128 && vv >= 0 && vv < NF) {
                float wlo = wl[(du + 1) * 3 + dv + 1];
                float who = wh[(du + 1) * 3 + dv + 1];
                int o = vv * 128 + uu;
                acc += wlo * g_aloT[img][o] + who * g_ahiT[img][o];
            }
        }
    g_ampoT[img][rem] = acc;
}

// inverse H DFT: block = (img, 4 v-cols), 128 threads; twiddle recurrence.
// Parity-uniform warps: y = 2*(t&63) + (t>>6).
__global__ void k_invH() {
    __shared__ float2 yE2[256], yO2[256];
    int t = threadIdx.x; // 128
    int img = blockIdx.x / 17;
    int vg = blockIdx.x % 17;
    int v0 = vg * 4;
    int cnt = (vg == 16) ? 1 : 4;
    for (int idx = t; idx < cnt * 64; idx += 128) {
        int vv = idx >> 6, uu = idx & 63;
        int base = (v0 + vv) * 128;
        float A0 = g_ampoT[img][base + uu],      P0 = g_phT[img][base + uu];
        float A1 = g_ampoT[img][base + 64 + uu], P1 = g_phT[img][base + 64 + uu];
        float c0 = __cosf(P0), s0 = __sinf(P0);
        float c1 = __cosf(P1), s1 = __sinf(P1);
        float y0r = A0 * c0, y0i = A0 * s0;
        float y1r = A1 * c1, y1i = A1 * s1;
        yE2[idx] = make_float2(y0r + y1r, y0i + y1i);
        yO2[idx] = make_float2(y0r - y1r, y0i - y1i);
    }
    __syncthreads();
    int y = ((t & 63) << 1) | (t >> 6);     // parity-uniform warps
    const float2* ysel = (y & 1) ? yO2 : yE2;
    float stx = g_cs[y], sty = g_sn[y];        // e^{+i yθ}
    float s2x = stx * stx - sty * sty;
    float s2y = 2.f * stx * sty;
    float wEx = 1.f, wEy = 0.f;
    float wOx = stx, wOy = sty;
    float zr[4], zi[4];
#pragma unroll
    for (int q = 0; q < 4; q++) { zr[q] = 0.f; zi[q] = 0.f; }
#pragma unroll 4
    for (int uu = 0; uu < 64; uu += 2) {
#pragma unroll
        for (int q = 0; q < 4; q++) {
            if (q < cnt) {
                float4 yv = *(const float4*)&ysel[q * 64 + uu];
                zr[q] += wEx * yv.x - wEy * yv.y + wOx * yv.z - wOy * yv.w;
                zi[q] += wEx * yv.y + wEy * yv.x + wOx * yv.w + wOy * yv.z;
            }
        }
        float nEx = wEx * s2x - wEy * s2y;
        wEy = wEy * s2x + wEx * s2y; wEx = nEx;
        float nOx = wOx * s2x - wOy * s2y;
        wOy = wOy * s2x + wOx * s2y; wOx = nOx;
    }
#pragma unroll
    for (int q = 0; q < 4; q++) {
        if (q < cnt) {
            g_zrT[img][(v0 + q) * 128 + y] = zr[q];
            g_ziT[img][(v0 + q) * 128 + y] = zi[q];
        }
    }
}

// inverse W (c2r): twiddle recurrence, two chains (odd/even v)
__global__ void k_invW() {
    __shared__ float2 zz[2][NF];    // (zr, zi)
    int t = threadIdx.x; // 128
    int img = blockIdx.x >> 6;
    int y0 = (blockIdx.x & 63) * 2;
    for (int idx = t; idx < 2 * NF; idx += 128) {
        int r = idx / NF, v = idx % NF;
        zz[r][v] = make_float2(g_zrT[img][v * 128 + y0 + r], g_ziT[img][v * 128 + y0 + r]);
    }
    __syncthreads();
    int r = t >> 6, x = t & 63;
    float z0 = zz[r][0].x, z64 = zz[r][64].x;
    float base = z0 + ((x & 1) ? -z64 : z64);
    float stx = g_cs[x], sty = g_sn[x];        // e^{+i xθ}
    float s2x = stx * stx - sty * sty;
    float s2y = 2.f * stx * sty;
    float w1x = stx, w1y = sty;                // angle xθ   (v=1 chain, odd v)
    float w2x = s2x, w2y = s2y;                // angle 2xθ  (v=2 chain, even v)
    float e = 0.f, o = 0.f;
#pragma unroll 8
    for (int v = 1; v < 64; v += 2) {
        float2 za = zz[r][v];
        o += za.x * w1x - za.y * w1y;
        if (v + 1 < 64) {
            float2 zb = zz[r][v + 1];
            e += zb.x * w2x - zb.y * w2y;
        }
        float n1x = w1x * s2x - w1y * s2y;
        w1y = w1y * s2x + w1x * s2y; w1x = n1x;
        float n2x = w2x * s2x - w2y * s2y;
        w2y = w2y * s2x + w2x * s2y; w2x = n2x;
    }
    e *= 2.0f; o *= 2.0f;
    float* kmflat = &g_km[0][0][0];
    kmflat[img * HW + (y0 + r) * 128 + x]      = (base + e + o) * (1.0f / 128.0f);
    kmflat[img * HW + (y0 + r) * 128 + x + 64] = (base + e - o) * (1.0f / 128.0f);
}

// ---------------- Wavelet unit (v path) ----------------
__global__ void k_haar() {
    int gid = blockIdx.x * 256 + threadIdx.x;
    int pos = gid & 4095, oc = (gid >> 12) & 63, b = gid >> 18;
    int i = pos >> 6, j = pos & 63;
    int ic = oc >> 2, f = oc & 3;
    const float* p = g_v[b][ic];
    float a = p[(2 * i) * 128 + 2 * j];
    float bb2 = p[(2 * i) * 128 + 2 * j + 1];
    float c2 = p[(2 * i + 1) * 128 + 2 * j];
    float d = p[(2 * i + 1) * 128 + 2 * j + 1];
    float r;
    if (f == 0)      r = (a + bb2 + c2 + d);
    else if (f == 1) r = (a - bb2 + c2 - d);
    else if (f == 2) r = (a + bb2 - c2 - d);
    else             r = (a - bb2 - c2 + d);
    g_y[b][oc][pos] = r * 0.5f;
}

// mlp_in: block = 32 pixels x 8 oc-groups(12 ocs), 512 blocks. Syncs are load-bearing.
__global__ void k_win(const float* __restrict__ mlp_in,
                      const float* __restrict__ bng, const float* __restrict__ bnb) {
    __shared__ float nv[32][49];
    __shared__ float sw[96 * 48];
    __shared__ float sg[48], sb[48];
    int t = threadIdx.x; // 256
    for (int i = t; i < 96 * 48; i += 256) sw[i] = mlp_in[i];
    if (t < 48) { sg[t] = bng[t] * rsqrtf(1.0f + 1e-5f); sb[t] = bnb[t]; }
    __syncthreads();                           // sg/sb visible before nv fill
    int b = blockIdx.x >> 7;                   // 128 blocks per batch
    int pos0 = (blockIdx.x & 127) * 32;
    for (int idx = t; idx < 32 * 48; idx += 256) {
        int ci = idx >> 5, pix = idx & 31;
        nv[pix][ci] = g_y[b][16 + ci][pos0 + pix] * sg[ci] + sb[ci];
    }
    __syncthreads();                           // nv + sw visible before compute
    int pix = t & 31, grp = t >> 5;            // 8 groups x 12 ocs
    int pos = pos0 + pix;
#pragma unroll
    for (int k = 0; k < 12; k++) {
        int oc = grp * 12 + k;
        float acc = 0.f;
#pragma unroll
        for (int ci = 0; ci < 48; ci++) acc += sw[oc * 48 + ci] * nv[pix][ci];
        g_m1[b][oc][pos] = acc;
    }
}

__global__ void k_wdw(const float* __restrict__ mlp_dw) {
    int gid = blockIdx.x * 256 + threadIdx.x;
    int pos = gid & 4095;
    int ch = (gid >> 12) % 96;
    int b = gid / (96 * 4096);
    int i = pos >> 6, j = pos & 63;
    const float* w = mlp_dw + ch * 9;
    const float* p = g_m1[b][ch];
    float acc = 0.f;
#pragma unroll
    for (int di = -1; di <= 1; di++)
#pragma unroll
        for (int dj = -1; dj <= 1; dj++) {
            int ii = i + di, jj = j + dj;
            if (ii >= 0 && ii < 64 && jj >= 0 && jj < 64)
                acc += w[(di + 1) * 3 + dj + 1] * p[ii * 64 + jj];
        }
    g_m2[b][ch][pos] = geluf(acc);
}

// mlp_out + residual + IWT: block = 64 pixels, 256 threads (4 oc-groups x 12)
__global__ void k_wout(const float* __restrict__ mlp_out, const float* __restrict__ rsp) {
    __shared__ float tile[96][64];   // 24KB
    __shared__ float sw[48 * 96];    // 18KB
    __shared__ float she[48][65];    // 12.2KB
    int t = threadIdx.x; // 256
    for (int i = t; i < 48 * 96; i += 256) sw[i] = mlp_out[i];
    int b = blockIdx.x >> 6;
    int pos0 = (blockIdx.x & 63) * 64;
    for (int idx = t; idx < 96 * 64; idx += 256) {
        int ch = idx >> 6, pix = idx & 63;
        tile[ch][pix] = g_m2[b][ch][pos0 + pix];
    }
    __syncthreads();
    float rs = rsp[0];
    int pix = t & 63, grp = t >> 6;            // 4 groups x 12 ocs
    int pos = pos0 + pix;
#pragma unroll
    for (int k = 0; k < 12; k++) {
        int oc = grp * 12 + k;
        float acc = 0.f;
#pragma unroll
        for (int ci = 0; ci < 96; ci++) acc += sw[oc * 96 + ci] * tile[ci][pix];
        she[oc][pix] = g_y[b][16 + oc][pos] + rs * acc;
    }
    __syncthreads();
    if (t < 64) {
        int p2 = pos0 + t;
        int i = p2 >> 6, j = p2 & 63;
#pragma unroll
        for (int c = 0; c < 16; c++) {
            float LL = g_y[b][c][p2];
            float* pl = &g_vm[b][c][0];
            pl[(2 * i) * 128 + 2 * j]         = LL;
            pl[(2 * i) * 128 + 2 * j + 1]     = she[c][t];
            pl[(2 * i + 1) * 128 + 2 * j]     = she[16 + c][t];
            pl[(2 * i + 1) * 128 + 2 * j + 1] = she[32 + c][t];
        }
    }
}

// ---------------- Gram partials: Sq, Sk, Skq per batch ----------------
__global__ void k_gram() {
    __shared__ float qt[16][257], kt[16][257];
    int t = threadIdx.x; // 256
    int b = blockIdx.y;
    int chunk = blockIdx.x;
    int n0 = chunk * 256;
    for (int i = t; i < 16 * 256; i += 256) {
        int c = i >> 8, n = i & 255;
        qt[c][n] = g_qm[b][c][n0 + n];
        kt[c][n] = g_km[b][c][n0 + n];
    }
    __syncthreads();
    for (int o = t; o < 768; o += 256) {
        int ty = o >> 8;
        int i = (o & 255) >> 4, j = o & 15;
        const float* pi = (ty == 1 || ty == 2) ? kt[i] : qt[i];
        const float* pj = (ty == 1) ? kt[j] : qt[j];
        float acc = 0.f;
#pragma unroll 8
        for (int n = 0; n < 256; n++) acc += pi[n] * pj[n];
        g_Sp[b][chunk][o] = acc;
    }
}

// ---------------- per-(batch,head) attention -> Th matrix ----------------
__global__ void k_attn(const float* __restrict__ We, const float* __restrict__ Wproj,
                       const float* __restrict__ rescale) {
    __shared__ float sS[768];       // Sq | Sk | Skq
    __shared__ float swh[16 * 64];  // We_h
    __shared__ float sA[3 * 16 * 64];
    __shared__ float sat[64 * 64];
    __shared__ float sinv[128];
    int t = threadIdx.x; // 256
    int h = blockIdx.x;  // 0..7
    int b = blockIdx.y;  // 0..3
    for (int i = t; i < 768; i += 256) {
        float acc = 0.f;
        for (int ch = 0; ch < 64; ch++) acc += g_Sp[b][ch][i];
        sS[i] = acc;
    }
    for (int i = t; i < 1024; i += 256) {
        int r = i >> 6, e = i & 63;
        swh[i] = We[r * 512 + h * 64 + e];
    }
    __syncthreads();
    float* Sq = sS; float* Sk = sS + 256; float* Skq = sS + 512;
    for (int i = t; i < 3 * 1024; i += 256) {
        int m = i >> 10;
        int rr = (i & 1023) >> 6, e = i & 63;
        const float* M = (m == 0) ? Sq : (m == 1) ? Sk : Skq;
        float acc = 0.f;
#pragma unroll
        for (int s = 0; s < 16; s++) acc += M[rr * 16 + s] * swh[s * 64 + e];
        sA[i] = acc;
    }
    __syncthreads();
    if (t < 128) {
        int e = t & 63, which = t >> 6;
        const float* A = (which == 0) ? sA : sA + 1024;
        float acc = 0.f;
#pragma unroll
        for (int r = 0; r < 16; r++) acc += swh[r * 64 + e] * A[r * 64 + e];
        float nrm = sqrtf(fmaxf(acc, 0.f));
        sinv[which * 64 + e] = 1.0f / fmaxf(nrm, 1e-12f);
    }
    __syncthreads();
    float rsc = rescale[h];
    for (int i = t; i < 4096; i += 256) {
        int d = i >> 6, e = i & 63;
        float acc = 0.f;
#pragma unroll
        for (int r = 0; r < 16; r++) acc += swh[r * 64 + d] * sA[2048 + r * 64 + e];
        sat[i] = acc * sinv[64 + d] * sinv[e] * rsc;
    }
    __syncthreads();
    if (t < 64) {
        int d = t;
        float mx = -1e30f;
        for (int e = 0; e < 64; e++) mx = fmaxf(mx, sat[d * 64 + e]);
        float sum = 0.f;
        for (int e = 0; e < 64; e++) {
            float ex = expf(sat[d * 64 + e] - mx);
            sat[d * 64 + e] = ex;
            sum += ex;
        }
        float is = 1.0f / sum;
        for (int e = 0; e < 64; e++) sat[d * 64 + e] *= is;
    }
    __syncthreads();
    // Q2[r][d] = sum_e We_h[r][e] * attn[d][e]
    for (int i = t; i < 1024; i += 256) {
        int r = i >> 6, d = i & 63;
        float acc = 0.f;
#pragma unroll
        for (int e = 0; e < 64; e++) acc += swh[r * 64 + e] * sat[d * 64 + e];
        sA[i] = acc;
    }
    __syncthreads();
    // Th[r][c] = sum_d Q2[r][d] * Wproj[h*64+d][c]
    for (int i = t; i < 1024; i += 256) {
        int r = i >> 6, c = i & 63;
        float acc = 0.f;
#pragma unroll
        for (int d = 0; d < 64; d++) acc += sA[r * 64 + d] * Wproj[(h * 64 + d) * 64 + c];
        g_Th[b * 8 + h][i] = acc;
    }
}

// ---------------- final: out = v_mix @ (sum_h Th) + bproj ----------------
__global__ void k_final(const float* __restrict__ bproj, float* __restrict__ out) {
    __shared__ float sT[1024];
    __shared__ float sb[64];
    int t = threadIdx.x; // 128
    int gid = blockIdx.x * 128 + t;
    int b = gid >> 14, n = gid & 16383;
    for (int i = t; i < 1024; i += 128) {
        float s = 0.f;
#pragma unroll
        for (int h = 0; h < 8; h++) s += g_Th[b * 8 + h][i];
        sT[i] = s;
    }
    if (t < 64) sb[t] = bproj[t];
    __syncthreads();
    float vr[16];
#pragma unroll
    for (int r = 0; r < 16; r++) vr[r] = g_vm[b][r][n];
    float4* op = (float4*)(out + (size_t)gid * 64);
#pragma unroll
    for (int c4 = 0; c4 < 16; c4++) {
        float4 o;
        float* oc = (float*)&o;
#pragma unroll
        for (int kk = 0; kk < 4; kk++) {
            int c = c4 * 4 + kk;
            float acc = sb[c];
#pragma unroll
            for (int r = 0; r < 16; r++) acc += vr[r] * sT[r * 64 + c];
            oc[kk] = acc;
        }
        op[c4] = o;
    }
}

// ---------------- launch ----------------
extern "C" void kernel_launch(void* const* d_in, const int* in_sizes, int n_in,
                              void* d_out, int out_size) {
    const float* x_in   = (const float*)d_in[0];
    const float* Wq     = (const float*)d_in[1];
    const float* Wk     = (const float*)d_in[2];
    const float* Wv     = (const float*)d_in[3];
    const float* Wr     = (const float*)d_in[4];
    const float* We     = (const float*)d_in[5];
    const float* qs_dw  = (const float*)d_in[6];
    const float* qs_pw  = (const float*)d_in[7];
    const float* qs_g   = (const float*)d_in[8];
    const float* al_pw  = (const float*)d_in[9];
    const float* al_dw  = (const float*)d_in[10];
    const float* ah_pw  = (const float*)d_in[11];
    const float* ah_dw  = (const float*)d_in[12];
    const float* ph_pw  = (const float*)d_in[13];
    const float* ph_s   = (const float*)d_in[14];
    const float* bng    = (const float*)d_in[15];
    const float* bnb    = (const float*)d_in[16];
    const float* mlp_in = (const float*)d_in[17];
    const float* mlp_dw = (const float*)d_in[18];
    const float* mlp_out= (const float*)d_in[19];
    const float* res_s  = (const float*)d_in[20];
    const float* rescale= (const float*)d_in[21];
    const float* Wproj  = (const float*)d_in[22];
    const float* bproj  = (const float*)d_in[23];
    float* out = (float*)d_out;

    // one-time side-stream/event setup (host-side resources only)
    static cudaStream_t s1 = nullptr, s2 = nullptr;
    static cudaEvent_t ev0 = nullptr, ev1 = nullptr, ev2 = nullptr, ev3 = nullptr;
    if (!s1) {
        cudaStreamCreateWithFlags(&s1, cudaStreamNonBlocking);
        cudaStreamCreateWithFlags(&s2, cudaStreamNonBlocking);
        cudaEventCreateWithFlags(&ev0, cudaEventDisableTiming);
        cudaEventCreateWithFlags(&ev1, cudaEventDisableTiming);
        cudaEventCreateWithFlags(&ev2, cudaEventDisableTiming);
        cudaEventCreateWithFlags(&ev3, cudaEventDisableTiming);
    }

    // init on stream 0; fork after it
    k_init<<<25, 128>>>(Wq, Wk, Wv, Wr);
    cudaEventRecord(ev0, 0);
    cudaStreamWaitEvent(s1, ev0, 0);

    // critical path (stream 0): k-projection then Fourier chain
    k_projk<<<512, 128>>>(x_in);
    k_fwdW<<<NIMG * 32, 288>>>();
    k_fwdH<<<NIMG * 17, 128>>>();
    k_pwf<<<(BB * FSZ) / 256, 256>>>(al_pw, ah_pw, ph_pw, ph_s);
    k_dwf<<<(NIMG * FSZ) / 256, 256>>>(al_dw, ah_dw);
    k_invH<<<NIMG * 17, 128>>>();
    k_invW<<<NIMG * 64, 128>>>();

    // side path (s1): q+v projection, then wavelet chain; spatial forks to s2
    k_projqv<<<512, 128, 0, s1>>>(x_in);
    cudaEventRecord(ev3, s1);
    cudaStreamWaitEvent(s2, ev3, 0);
    k_spatial<<<BB * 64, 256, 0, s2>>>(qs_dw, qs_pw, qs_g);
    cudaEventRecord(ev2, s2);

    k_haar<<<(BB * 64 * HWH) / 256, 256, 0, s1>>>();
    k_win<<<(BB * HWH) / 32, 256, 0, s1>>>(mlp_in, bng, bnb);
    k_wdw<<<(BB * 96 * HWH) / 256, 256, 0, s1>>>(mlp_dw);
    k_wout<<<BB * 64, 256, 0, s1>>>(mlp_out, res_s);
    cudaEventRecord(ev1, s1);

    // join spatial (gram needs qm + km)
    cudaStreamWaitEvent(0, ev2, 0);
    {
        dim3 g(64, BB);
        k_gram<<<g, 256>>>();
    }
    {
        dim3 g(8, BB);
        k_attn<<<g, 256>>>(We, Wproj, rescale);
    }
    // join wavelet (final needs vm)
    cudaStreamWaitEvent(0, ev1, 0);
    k_final<<<512, 128>>>(bproj, out);
}

// round 17
// speedup vs baseline: 1.0398x; 1.0398x over previous
#include <cuda_runtime.h>
#include <math.h>

// Problem constants
#define BB 4
#define HH 128
#define WW 128
#define CIN 64
#define DR 16
#define HW 16384          // 128*128
#define NIMG 64           // B*DR
#define NF 65             // rfft width bins
#define FSZ (NF*128)      // 8320 floats per transposed freq image [v][u]
#define HWH 4096          // 64*64 (wavelet half-res)

// ---------------- device scratch (static, allocation-free) ----------------
__device__ float g_Wc[CIN][48];                 // combined qkv->dim weights
__device__ float g_q [BB][DR][HW];
__device__ float g_k [BB][DR][HW];
__device__ float g_v [BB][DR][HW];
__device__ float g_qm[BB][DR][HW];
__device__ float g_km[BB][DR][HW];
__device__ float g_vm[BB][DR][HW];
// Fourier scratch, TRANSPOSED layout [img][v][u] (u contiguous)
__device__ float g_zrT [NIMG][FSZ];
__device__ float g_ziT [NIMG][FSZ];
__device__ float g_ampT[NIMG][FSZ];
__device__ float g_phT [NIMG][FSZ];
__device__ float g_aloT[NIMG][FSZ];
__device__ float g_ahiT[NIMG][FSZ];
__device__ float g_ampoT[NIMG][FSZ];
// Wavelet scratch
__device__ float g_y [BB][64][HWH];
__device__ float g_m1[BB][96][HWH];
__device__ float g_m2[BB][96][HWH];
// Small matrices
__device__ float g_Sp[BB][64][768];             // partial Grams
__device__ float g_Th[BB * 8][1024];            // per-(batch,head) epilogue matrices
__device__ float g_cs[128], g_sn[128];          // twiddles

__device__ __forceinline__ float geluf(float x) {
    return 0.5f * x * (1.0f + erff(x * 0.70710678118654752440f));
}

// ---------------- init: combined weights + twiddles (parallel) ----------------
__global__ void k_init(const float* __restrict__ Wq, const float* __restrict__ Wk,
                       const float* __restrict__ Wv, const float* __restrict__ Wr) {
    int t = threadIdx.x; // 128
    int bx = blockIdx.x; // 0..24
    if (bx == 24) {
        float th = 6.283185307179586f * (float)t / 128.0f;
        g_cs[t] = cosf(th);
        g_sn[t] = sinf(th);
        return;
    }
    int o = bx * 128 + t;            // 0..3071
    int i = o / 48, j = o % 48;
    const float* Wsel = (j < 16) ? Wq : (j < 32) ? Wk : Wv;
    int jj = j & 15;
    float acc = 0.f;
#pragma unroll 4
    for (int f = 0; f < 512; f++) acc += Wsel[i * 512 + f] * Wr[f * 16 + jj];
    g_Wc[i][j] = acc;
}

// ---------------- k-only projection (critical path: feeds Fourier), half-batch ----------------
__global__ void k_projk(const float* __restrict__ x, int blkBase) {
    __shared__ float sW[CIN * 16];
    int t = threadIdx.x; // 128
    for (int i = t; i < CIN * 16; i += 128) {
        int row = i >> 4, col = i & 15;
        sW[i] = g_Wc[row][16 + col];
    }
    __syncthreads();
    int gid = (blockIdx.x + blkBase) * 128 + t;  // half of 0..65535
    int b = gid >> 14, n = gid & 16383;
    float xr[64];
    const float4* xp = (const float4*)(x + (size_t)gid * 64);
#pragma unroll
    for (int i = 0; i < 16; i++) {
        float4 f = xp[i];
        xr[4 * i] = f.x; xr[4 * i + 1] = f.y; xr[4 * i + 2] = f.z; xr[4 * i + 3] = f.w;
    }
    float acc[16];
#pragma unroll
    for (int j = 0; j < 16; j++) acc[j] = 0.f;
#pragma unroll
    for (int i = 0; i < 64; i++) {
        float xi = xr[i];
#pragma unroll
        for (int j = 0; j < 16; j++) acc[j] += xi * sW[i * 16 + j];
    }
#pragma unroll
    for (int j = 0; j < 16; j++) g_k[b][j][n] = acc[j];
}

// ---------------- q+v projection (side streams: feeds spatial + wavelet) ----------------
__global__ void k_projqv(const float* __restrict__ x) {
    __shared__ float sW[CIN * 32];
    int t = threadIdx.x; // 128
    for (int i = t; i < CIN * 32; i += 128) {
        int row = i >> 5, col = i & 31;
        sW[i] = g_Wc[row][(col < 16) ? col : (col + 16)];   // q cols 0-15, v cols 32-47
    }
    __syncthreads();
    int gid = blockIdx.x * 128 + t;              // 0..65535
    int b = gid >> 14, n = gid & 16383;
    float xr[64];
    const float4* xp = (const float4*)(x + (size_t)gid * 64);
#pragma unroll
    for (int i = 0; i < 16; i++) {
        float4 f = xp[i];
        xr[4 * i] = f.x; xr[4 * i + 1] = f.y; xr[4 * i + 2] = f.z; xr[4 * i + 3] = f.w;
    }
    float acc[32];
#pragma unroll
    for (int j = 0; j < 32; j++) acc[j] = 0.f;
#pragma unroll
    for (int i = 0; i < 64; i++) {
        float xi = xr[i];
#pragma unroll
        for (int j = 0; j < 32; j++) acc[j] += xi * sW[i * 32 + j];
    }
#pragma unroll
    for (int j = 0; j < 16; j++) {
        g_q[b][j][n] = acc[j];
        g_v[b][j][n] = acc[16 + j];
    }
}

// ---------------- Spatial unit (q path) — fused dw+gelu+pw ----------------
__global__ void k_spatial(const float* __restrict__ dw, const float* __restrict__ pw,
                          const float* __restrict__ gamma) {
    __shared__ float sin_[16][324];   // 18x18 halo tiles, 16 channels
    __shared__ float sdw[144], spw[256], sg[16];
    int t = threadIdx.x; // 256
    int b = blockIdx.x >> 6;
    int tile = blockIdx.x & 63;
    int i0 = (tile >> 3) * 16, j0 = (tile & 7) * 16;
    if (t < 144) sdw[t] = dw[t];
    spw[t] = pw[t];
    if (t < 16) sg[t] = gamma[t];
    for (int idx = t; idx < 16 * 324; idx += 256) {
        int c = idx / 324, rem = idx % 324;
        int ii = rem / 18, jj = rem % 18;
        int gi = i0 - 1 + ii, gj = j0 - 1 + jj;
        float v = 0.f;
        if (gi >= 0 && gi < 128 && gj >= 0 && gj < 128) v = g_q[b][c][gi * 128 + gj];
        sin_[c][rem] = v;
    }
    __syncthreads();
    int li = t >> 4, lj = t & 15;
    float m[16];
#pragma unroll
    for (int c = 0; c < 16; c++) {
        float acc = 0.f;
#pragma unroll
        for (int di = 0; di < 3; di++)
#pragma unroll
            for (int dj = 0; dj < 3; dj++)
                acc += sdw[c * 9 + di * 3 + dj] * sin_[c][(li + di) * 18 + (lj + dj)];
        m[c] = geluf(acc);
    }
    int pix = (i0 + li) * 128 + (j0 + lj);
#pragma unroll
    for (int c = 0; c < 16; c++) {
        float acc = 0.f;
#pragma unroll
        for (int ci = 0; ci < 16; ci++) acc += spw[c * 16 + ci] * m[ci];
        g_qm[b][c][pix] = sin_[c][(li + 1) * 18 + (lj + 1)] + sg[c] * acc;
    }
}

// ---------------- Fourier unit (k path): radix-2 split DFTs, twiddle recurrence ----------------
// fwd W: per block 4 rows; half-image grid via imgBase
__global__ void k_fwdW(int imgBase) {
    __shared__ float raw[512], rE[256], rO[256];
    int t = threadIdx.x; // 288
    int img = imgBase + (blockIdx.x >> 5);
    int y0 = (blockIdx.x & 31) * 4;
    const float* kflat = &g_k[0][0][0];
    for (int idx = t; idx < 512; idx += 288) {
        int r = idx >> 7, x = idx & 127;
        raw[idx] = kflat[img * HW + (y0 + r) * 128 + x];
    }
    __syncthreads();
    for (int idx = t; idx < 256; idx += 288) {
        int r = idx >> 6, x = idx & 63;
        float a = raw[r * 128 + x], bv = raw[r * 128 + 64 + x];
        rE[idx] = a + bv;
        rO[idx] = a - bv;
    }
    __syncthreads();
    if (t < 260) {
        int r = t / 65, v = t % 65;
        const float* rp = (v & 1) ? (rO + r * 64) : (rE + r * 64);
        float stx = g_cs[v & 127], sty = g_sn[v & 127];   // e^{+i vθ}
        float s2x = stx * stx - sty * sty;
        float s2y = 2.f * stx * sty;
        float wEx = 1.f, wEy = 0.f;        // angle 0
        float wOx = stx, wOy = sty;        // angle vθ
        float ar = 0.f, ai = 0.f;
#pragma unroll 8
        for (int x = 0; x < 64; x += 2) {
            float2 rv2 = *(const float2*)&rp[x];
            ar += rv2.x * wEx + rv2.y * wOx;
            ai -= rv2.x * wEy + rv2.y * wOy;
            float nEx = wEx * s2x - wEy * s2y;
            wEy = wEy * s2x + wEx * s2y; wEx = nEx;
            float nOx = wOx * s2x - wOy * s2y;
            wOy = wOy * s2x + wOx * s2y; wOx = nOx;
        }
        g_zrT[img][v * 128 + y0 + r] = ar;
        g_ziT[img][v * 128 + y0 + r] = ai;
    }
}

// fwd H + amp/phase: block = (img, 4 v-cols), 128 threads; parity-uniform warps.
__global__ void k_fwdH(int imgBase) {
    __shared__ float2 zE2[256], zO2[256];   // (re, im), 4 cols x 64
    int t = threadIdx.x; // 128
    int img = imgBase + blockIdx.x / 17;
    int vg = blockIdx.x % 17;
    int v0 = vg * 4;
    int cnt = (vg == 16) ? 1 : 4;
    for (int idx = t; idx < cnt * 64; idx += 128) {
        int vv = idx >> 6, yy = idx & 63;
        int base = (v0 + vv) * 128;
        float a0 = g_zrT[img][base + yy], a1 = g_zrT[img][base + 64 + yy];
        float b0 = g_ziT[img][base + yy], b1 = g_ziT[img][base + 64 + yy];
        zE2[idx] = make_float2(a0 + a1, b0 + b1);
        zO2[idx] = make_float2(a0 - a1, b0 - b1);
    }
    __syncthreads();
    int u = ((t & 63) << 1) | (t >> 6);     // warps 0-1: even u; warps 2-3: odd u
    const float2* zsel = (u & 1) ? zO2 : zE2;
    float stx = g_cs[u], sty = g_sn[u];        // e^{+i uθ}
    float s2x = stx * stx - sty * sty;
    float s2y = 2.f * stx * sty;
    float wEx = 1.f, wEy = 0.f;                // angle 0 (yy even chain)
    float wOx = stx, wOy = sty;                // angle uθ (yy odd chain)
    float xr[4], xi[4];
#pragma unroll
    for (int q = 0; q < 4; q++) { xr[q] = 0.f; xi[q] = 0.f; }
#pragma unroll 4
    for (int yy = 0; yy < 64; yy += 2) {
#pragma unroll
        for (int q = 0; q < 4; q++) {
            if (q < cnt) {
                float4 z2 = *(const float4*)&zsel[q * 64 + yy];
                xr[q] += wEx * z2.x + wEy * z2.y + wOx * z2.z + wOy * z2.w;
                xi[q] += wEx * z2.y - wEy * z2.x + wOx * z2.w - wOy * z2.z;
            }
        }
        float nEx = wEx * s2x - wEy * s2y;
        wEy = wEy * s2x + wEx * s2y; wEx = nEx;
        float nOx = wOx * s2x - wOy * s2y;
        wOy = wOy * s2x + wOx * s2y; wOx = nOx;
    }
#pragma unroll
    for (int q = 0; q < 4; q++) {
        if (q < cnt) {
            float a = xr[q] * (1.0f / 128.0f), bq = xi[q] * (1.0f / 128.0f);
            int o = (v0 + q) * 128 + u;
            g_ampT[img][o] = sqrtf(a * a + bq * bq);
            g_phT[img][o]  = atan2f(bq, a);
        }
    }
}

// pointwise freq-domain convs (transposed layout), half-batch via bBase
__global__ void k_pwf(const float* __restrict__ alpw, const float* __restrict__ ahpw,
                      const float* __restrict__ phpw, const float* __restrict__ phs,
                      int bBase) {
    __shared__ float wl[256], wh[256], wp[256];
    int t = threadIdx.x; // 256
    wl[t] = alpw[t]; wh[t] = ahpw[t]; wp[t] = phpw[t];
    __syncthreads();
    int gid = blockIdx.x * 256 + t;          // < 2*FSZ = 16640
    int b = bBase + gid / FSZ;
    int rem = gid % FSZ;
    int v = rem >> 7, u = rem & 127;
    float a[16], p[16];
#pragma unroll
    for (int c = 0; c < 16; c++) { a[c] = g_ampT[b * 16 + c][rem]; p[c] = g_phT[b * 16 + c][rem]; }
    float yy = (float)u * (1.0f / 127.0f);
    float xx = (float)v * (1.0f / 64.0f);
    float rr = sqrtf(yy * yy + xx * xx);
    float low = 1.0f / (1.0f + __expf(-(0.25f - rr) * 20.0f));
    float high = 1.0f - low;
    float ps = phs[0];
#pragma unroll
    for (int c = 0; c < 16; c++) {
        float s1 = 0.f, s2 = 0.f, s3 = 0.f;
#pragma unroll
        for (int ci = 0; ci < 16; ci++) {
            s1 += wl[c * 16 + ci] * a[ci];
            s2 += wh[c * 16 + ci] * a[ci];
            s3 += wp[c * 16 + ci] * p[ci];
        }
        g_aloT[b * 16 + c][rem] = geluf(s1 * low);
        g_ahiT[b * 16 + c][rem] = geluf(s2 * high);
        g_phT [b * 16 + c][rem] = p[c] + ps * s3;
    }
}

__global__ void k_dwf(const float* __restrict__ aldw, const float* __restrict__ ahdw,
                      int imgBase) {
    int gid = blockIdx.x * 256 + threadIdx.x;   // < 32*FSZ = 266240
    int img = imgBase + gid / FSZ;
    int rem = gid % FSZ;
    int v = rem >> 7, u = rem & 127;
    int c = img & 15;
    const float* wl = aldw + c * 9;
    const float* wh = ahdw + c * 9;
    float acc = 0.f;
#pragma unroll
    for (int du = -1; du <= 1; du++)
#pragma unroll
        for (int dv = -1; dv <= 1; dv++) {
            int uu = u + du, vv = v + dv;
            if (uu >= 0 && uu < 128 && vv >= 0 && vv < NF) {
                float wlo = wl[(du + 1) * 3 + dv + 1];
                float who = wh[(du + 1) * 3 + dv + 1];
                int o = vv * 128 + uu;
                acc += wlo * g_aloT[img][o] + who * g_ahiT[img][o];
            }
        }
    g_ampoT[img][rem] = acc;
}

// inverse H DFT: block = (img, 4 v-cols), 128 threads; parity-uniform warps.
__global__ void k_invH(int imgBase) {
    __shared__ float2 yE2[256], yO2[256];
    int t = threadIdx.x; // 128
    int img = imgBase + blockIdx.x / 17;
    int vg = blockIdx.x % 17;
    int v0 = vg * 4;
    int cnt = (vg == 16) ? 1 : 4;
    for (int idx = t; idx < cnt * 64; idx += 128) {
        int vv = idx >> 6, uu = idx & 63;
        int base = (v0 + vv) * 128;
        float A0 = g_ampoT[img][base + uu],      P0 = g_phT[img][base + uu];
        float A1 = g_ampoT[img][base + 64 + uu], P1 = g_phT[img][base + 64 + uu];
        float c0 = __cosf(P0), s0 = __sinf(P0);
        float c1 = __cosf(P1), s1 = __sinf(P1);
        float y0r = A0 * c0, y0i = A0 * s0;
        float y1r = A1 * c1, y1i = A1 * s1;
        yE2[idx] = make_float2(y0r + y1r, y0i + y1i);
        yO2[idx] = make_float2(y0r - y1r, y0i - y1i);
    }
    __syncthreads();
    int y = ((t & 63) << 1) | (t >> 6);     // parity-uniform warps
    const float2* ysel = (y & 1) ? yO2 : yE2;
    float stx = g_cs[y], sty = g_sn[y];        // e^{+i yθ}
    float s2x = stx * stx - sty * sty;
    float s2y = 2.f * stx * sty;
    float wEx = 1.f, wEy = 0.f;
    float wOx = stx, wOy = sty;
    float zr[4], zi[4];
#pragma unroll
    for (int q = 0; q < 4; q++) { zr[q] = 0.f; zi[q] = 0.f; }
#pragma unroll 4
    for (int uu = 0; uu < 64; uu += 2) {
#pragma unroll
        for (int q = 0; q < 4; q++) {
            if (q < cnt) {
                float4 yv = *(const float4*)&ysel[q * 64 + uu];
                zr[q] += wEx * yv.x - wEy * yv.y + wOx * yv.z - wOy * yv.w;
                zi[q] += wEx * yv.y + wEy * yv.x + wOx * yv.w + wOy * yv.z;
            }
        }
        float nEx = wEx * s2x - wEy * s2y;
        wEy = wEy * s2x + wEx * s2y; wEx = nEx;
        float nOx = wOx * s2x - wOy * s2y;
        wOy = wOy * s2x + wOx * s2y; wOx = nOx;
    }
#pragma unroll
    for (int q = 0; q < 4; q++) {
        if (q < cnt) {
            g_zrT[img][(v0 + q) * 128 + y] = zr[q];
            g_ziT[img][(v0 + q) * 128 + y] = zi[q];
        }
    }
}

// inverse W (c2r): twiddle recurrence, two chains (odd/even v)
__global__ void k_invW(int imgBase) {
    __shared__ float2 zz[2][NF];    // (zr, zi)
    int t = threadIdx.x; // 128
    int img = imgBase + (blockIdx.x >> 6);
    int y0 = (blockIdx.x & 63) * 2;
    for (int idx = t; idx < 2 * NF; idx += 128) {
        int r = idx / NF, v = idx % NF;
        zz[r][v] = make_float2(g_zrT[img][v * 128 + y0 + r], g_ziT[img][v * 128 + y0 + r]);
    }
    __syncthreads();
    int r = t >> 6, x = t & 63;
    float z0 = zz[r][0].x, z64 = zz[r][64].x;
    float base = z0 + ((x & 1) ? -z64 : z64);
    float stx = g_cs[x], sty = g_sn[x];        // e^{+i xθ}
    float s2x = stx * stx - sty * sty;
    float s2y = 2.f * stx * sty;
    float w1x = stx, w1y = sty;                // angle xθ   (v=1 chain, odd v)
    float w2x = s2x, w2y = s2y;                // angle 2xθ  (v=2 chain, even v)
    float e = 0.f, o = 0.f;
#pragma unroll 8
    for (int v = 1; v < 64; v += 2) {
        float2 za = zz[r][v];
        o += za.x * w1x - za.y * w1y;
        if (v + 1 < 64) {
            float2 zb = zz[r][v + 1];
            e += zb.x * w2x - zb.y * w2y;
        }
        float n1x = w1x * s2x - w1y * s2y;
        w1y = w1y * s2x + w1x * s2y; w1x = n1x;
        float n2x = w2x * s2x - w2y * s2y;
        w2y = w2y * s2x + w2x * s2y; w2x = n2x;
    }
    e *= 2.0f; o *= 2.0f;
    float* kmflat = &g_km[0][0][0];
    kmflat[img * HW + (y0 + r) * 128 + x]      = (base + e + o) * (1.0f / 128.0f);
    kmflat[img * HW + (y0 + r) * 128 + x + 64] = (base + e - o) * (1.0f / 128.0f);
}

// ---------------- Wavelet unit (v path) ----------------
__global__ void k_haar() {
    int gid = blockIdx.x * 256 + threadIdx.x;
    int pos = gid & 4095, oc = (gid >> 12) & 63, b = gid >> 18;
    int i = pos >> 6, j = pos & 63;
    int ic = oc >> 2, f = oc & 3;
    const float* p = g_v[b][ic];
    float a = p[(2 * i) * 128 + 2 * j];
    float bb2 = p[(2 * i) * 128 + 2 * j + 1];
    float c2 = p[(2 * i + 1) * 128 + 2 * j];
    float d = p[(2 * i + 1) * 128 + 2 * j + 1];
    float r;
    if (f == 0)      r = (a + bb2 + c2 + d);
    else if (f == 1) r = (a - bb2 + c2 - d);
    else if (f == 2) r = (a + bb2 - c2 - d);
    else             r = (a - bb2 - c2 + d);
    g_y[b][oc][pos] = r * 0.5f;
}

// mlp_in: block = 32 pixels x 8 oc-groups(12 ocs), 512 blocks. Syncs are load-bearing.
__global__ void k_win(const float* __restrict__ mlp_in,
                      const float* __restrict__ bng, const float* __restrict__ bnb) {
    __shared__ float nv[32][49];
    __shared__ float sw[96 * 48];
    __shared__ float sg[48], sb[48];
    int t = threadIdx.x; // 256
    for (int i = t; i < 96 * 48; i += 256) sw[i] = mlp_in[i];
    if (t < 48) { sg[t] = bng[t] * rsqrtf(1.0f + 1e-5f); sb[t] = bnb[t]; }
    __syncthreads();                           // sg/sb visible before nv fill
    int b = blockIdx.x >> 7;                   // 128 blocks per batch
    int pos0 = (blockIdx.x & 127) * 32;
    for (int idx = t; idx < 32 * 48; idx += 256) {
        int ci = idx >> 5, pix = idx & 31;
        nv[pix][ci] = g_y[b][16 + ci][pos0 + pix] * sg[ci] + sb[ci];
    }
    __syncthreads();                           // nv + sw visible before compute
    int pix = t & 31, grp = t >> 5;            // 8 groups x 12 ocs
    int pos = pos0 + pix;
#pragma unroll
    for (int k = 0; k < 12; k++) {
        int oc = grp * 12 + k;
        float acc = 0.f;
#pragma unroll
        for (int ci = 0; ci < 48; ci++) acc += sw[oc * 48 + ci] * nv[pix][ci];
        g_m1[b][oc][pos] = acc;
    }
}

__global__ void k_wdw(const float* __restrict__ mlp_dw) {
    int gid = blockIdx.x * 256 + threadIdx.x;
    int pos = gid & 4095;
    int ch = (gid >> 12) % 96;
    int b = gid / (96 * 4096);
    int i = pos >> 6, j = pos & 63;
    const float* w = mlp_dw + ch * 9;
    const float* p = g_m1[b][ch];
    float acc = 0.f;
#pragma unroll
    for (int di = -1; di <= 1; di++)
#pragma unroll
        for (int dj = -1; dj <= 1; dj++) {
            int ii = i + di, jj = j + dj;
            if (ii >= 0 && ii < 64 && jj >= 0 && jj < 64)
                acc += w[(di + 1) * 3 + dj + 1] * p[ii * 64 + jj];
        }
    g_m2[b][ch][pos] = geluf(acc);
}

// mlp_out + residual + IWT: block = 64 pixels, 256 threads (4 oc-groups x 12)
__global__ void k_wout(const float* __restrict__ mlp_out, const float* __restrict__ rsp) {
    __shared__ float tile[96][64];   // 24KB
    __shared__ float sw[48 * 96];    // 18KB
    __shared__ float she[48][65];    // 12.2KB
    int t = threadIdx.x; // 256
    for (int i = t; i < 48 * 96; i += 256) sw[i] = mlp_out[i];
    int b = blockIdx.x >> 6;
    int pos0 = (blockIdx.x & 63) * 64;
    for (int idx = t; idx < 96 * 64; idx += 256) {
        int ch = idx >> 6, pix = idx & 63;
        tile[ch][pix] = g_m2[b][ch][pos0 + pix];
    }
    __syncthreads();
    float rs = rsp[0];
    int pix = t & 63, grp = t >> 6;            // 4 groups x 12 ocs
    int pos = pos0 + pix;
#pragma unroll
    for (int k = 0; k < 12; k++) {
        int oc = grp * 12 + k;
        float acc = 0.f;
#pragma unroll
        for (int ci = 0; ci < 96; ci++) acc += sw[oc * 96 + ci] * tile[ci][pix];
        she[oc][pix] = g_y[b][16 + oc][pos] + rs * acc;
    }
    __syncthreads();
    if (t < 64) {
        int p2 = pos0 + t;
        int i = p2 >> 6, j = p2 & 63;
#pragma unroll
        for (int c = 0; c < 16; c++) {
            float LL = g_y[b][c][p2];
            float* pl = &g_vm[b][c][0];
            pl[(2 * i) * 128 + 2 * j]         = LL;
            pl[(2 * i) * 128 + 2 * j + 1]     = she[c][t];
            pl[(2 * i + 1) * 128 + 2 * j]     = she[16 + c][t];
            pl[(2 * i + 1) * 128 + 2 * j + 1] = she[32 + c][t];
        }
    }
}

// ---------------- Gram partials: Sq, Sk, Skq per batch ----------------
__global__ void k_gram() {
    __shared__ float qt[16][257], kt[16][257];
    int t = threadIdx.x; // 256
    int b = blockIdx.y;
    int chunk = blockIdx.x;
    int n0 = chunk * 256;
    for (int i = t; i < 16 * 256; i += 256) {
        int c = i >> 8, n = i & 255;
        qt[c][n] = g_qm[b][c][n0 + n];
        kt[c][n] = g_km[b][c][n0 + n];
    }
    __syncthreads();
    for (int o = t; o < 768; o += 256) {
        int ty = o >> 8;
        int i = (o & 255) >> 4, j = o & 15;
        const float* pi = (ty == 1 || ty == 2) ? kt[i] : qt[i];
        const float* pj = (ty == 1) ? kt[j] : qt[j];
        float acc = 0.f;
#pragma unroll 8
        for (int n = 0; n < 256; n++) acc += pi[n] * pj[n];
        g_Sp[b][chunk][o] = acc;
    }
}

// ---------------- per-(batch,head) attention -> Th matrix ----------------
__global__ void k_attn(const float* __restrict__ We, const float* __restrict__ Wproj,
                       const float* __restrict__ rescale) {
    __shared__ float sS[768];       // Sq | Sk | Skq
    __shared__ float swh[16 * 64];  // We_h
    __shared__ float sA[3 * 16 * 64];
    __shared__ float sat[64 * 64];
    __shared__ float sinv[128];
    int t = threadIdx.x; // 256
    int h = blockIdx.x;  // 0..7
    int b = blockIdx.y;  // 0..3
    for (int i = t; i < 768; i += 256) {
        float acc = 0.f;
        for (int ch = 0; ch < 64; ch++) acc += g_Sp[b][ch][i];
        sS[i] = acc;
    }
    for (int i = t; i < 1024; i += 256) {
        int r = i >> 6, e = i & 63;
        swh[i] = We[r * 512 + h * 64 + e];
    }
    __syncthreads();
    float* Sq = sS; float* Sk = sS + 256; float* Skq = sS + 512;
    for (int i = t; i < 3 * 1024; i += 256) {
        int m = i >> 10;
        int rr = (i & 1023) >> 6, e = i & 63;
        const float* M = (m == 0) ? Sq : (m == 1) ? Sk : Skq;
        float acc = 0.f;
#pragma unroll
        for (int s = 0; s < 16; s++) acc += M[rr * 16 + s] * swh[s * 64 + e];
        sA[i] = acc;
    }
    __syncthreads();
    if (t < 128) {
        int e = t & 63, which = t >> 6;
        const float* A = (which == 0) ? sA : sA + 1024;
        float acc = 0.f;
#pragma unroll
        for (int r = 0; r < 16; r++) acc += swh[r * 64 + e] * A[r * 64 + e];
        float nrm = sqrtf(fmaxf(acc, 0.f));
        sinv[which * 64 + e] = 1.0f / fmaxf(nrm, 1e-12f);
    }
    __syncthreads();
    float rsc = rescale[h];
    for (int i = t; i < 4096; i += 256) {
        int d = i >> 6, e = i & 63;
        float acc = 0.f;
#pragma unroll
        for (int r = 0; r < 16; r++) acc += swh[r * 64 + d] * sA[2048 + r * 64 + e];
        sat[i] = acc * sinv[64 + d] * sinv[e] * rsc;
    }
    __syncthreads();
    if (t < 64) {
        int d = t;
        float mx = -1e30f;
        for (int e = 0; e < 64; e++) mx = fmaxf(mx, sat[d * 64 + e]);
        float sum = 0.f;
        for (int e = 0; e < 64; e++) {
            float ex = expf(sat[d * 64 + e] - mx);
            sat[d * 64 + e] = ex;
            sum += ex;
        }
        float is = 1.0f / sum;
        for (int e = 0; e < 64; e++) sat[d * 64 + e] *= is;
    }
    __syncthreads();
    // Q2[r][d] = sum_e We_h[r][e] * attn[d][e]
    for (int i = t; i < 1024; i += 256) {
        int r = i >> 6, d = i & 63;
        float acc = 0.f;
#pragma unroll
        for (int e = 0; e < 64; e++) acc += swh[r * 64 + e] * sat[d * 64 + e];
        sA[i] = acc;
    }
    __syncthreads();
    // Th[r][c] = sum_d Q2[r][d] * Wproj[h*64+d][c]
    for (int i = t; i < 1024; i += 256) {
        int r = i >> 6, c = i & 63;
        float acc = 0.f;
#pragma unroll
        for (int d = 0; d < 64; d++) acc += sA[r * 64 + d] * Wproj[(h * 64 + d) * 64 + c];
        g_Th[b * 8 + h][i] = acc;
    }
}

// ---------------- final: out = v_mix @ (sum_h Th) + bproj ----------------
__global__ void k_final(const float* __restrict__ bproj, float* __restrict__ out) {
    __shared__ float sT[1024];
    __shared__ float sb[64];
    int t = threadIdx.x; // 128
    int gid = blockIdx.x * 128 + t;
    int b = gid >> 14, n = gid & 16383;
    for (int i = t; i < 1024; i += 128) {
        float s = 0.f;
#pragma unroll
        for (int h = 0; h < 8; h++) s += g_Th[b * 8 + h][i];
        sT[i] = s;
    }
    if (t < 64) sb[t] = bproj[t];
    __syncthreads();
    float vr[16];
#pragma unroll
    for (int r = 0; r < 16; r++) vr[r] = g_vm[b][r][n];
    float4* op = (float4*)(out + (size_t)gid * 64);
#pragma unroll
    for (int c4 = 0; c4 < 16; c4++) {
        float4 o;
        float* oc = (float*)&o;
#pragma unroll
        for (int kk = 0; kk < 4; kk++) {
            int c = c4 * 4 + kk;
            float acc = sb[c];
#pragma unroll
            for (int r = 0; r < 16; r++) acc += vr[r] * sT[r * 64 + c];
            oc[kk] = acc;
        }
        op[c4] = o;
    }
}

// ---------------- launch ----------------
extern "C" void kernel_launch(void* const* d_in, const int* in_sizes, int n_in,
                              void* d_out, int out_size) {
    const float* x_in   = (const float*)d_in[0];
    const float* Wq     = (const float*)d_in[1];
    const float* Wk     = (const float*)d_in[2];
    const float* Wv     = (const float*)d_in[3];
    const float* Wr     = (const float*)d_in[4];
    const float* We     = (const float*)d_in[5];
    const float* qs_dw  = (const float*)d_in[6];
    const float* qs_pw  = (const float*)d_in[7];
    const float* qs_g   = (const float*)d_in[8];
    const float* al_pw  = (const float*)d_in[9];
    const float* al_dw  = (const float*)d_in[10];
    const float* ah_pw  = (const float*)d_in[11];
    const float* ah_dw  = (const float*)d_in[12];
    const float* ph_pw  = (const float*)d_in[13];
    const float* ph_s   = (const float*)d_in[14];
    const float* bng    = (const float*)d_in[15];
    const float* bnb    = (const float*)d_in[16];
    const float* mlp_in = (const float*)d_in[17];
    const float* mlp_dw = (const float*)d_in[18];
    const float* mlp_out= (const float*)d_in[19];
    const float* res_s  = (const float*)d_in[20];
    const float* rescale= (const float*)d_in[21];
    const float* Wproj  = (const float*)d_in[22];
    const float* bproj  = (const float*)d_in[23];
    float* out = (float*)d_out;

    // one-time side-stream/event setup (host-side resources only)
    static cudaStream_t s1 = nullptr, s2 = nullptr, s3 = nullptr;
    static cudaEvent_t ev0 = nullptr, ev1 = nullptr, ev2 = nullptr, ev3 = nullptr, ev4 = nullptr;
    if (!s1) {
        cudaStreamCreateWithFlags(&s1, cudaStreamNonBlocking);
        cudaStreamCreateWithFlags(&s2, cudaStreamNonBlocking);
        cudaStreamCreateWithFlags(&s3, cudaStreamNonBlocking);
        cudaEventCreateWithFlags(&ev0, cudaEventDisableTiming);
        cudaEventCreateWithFlags(&ev1, cudaEventDisableTiming);
        cudaEventCreateWithFlags(&ev2, cudaEventDisableTiming);
        cudaEventCreateWithFlags(&ev3, cudaEventDisableTiming);
        cudaEventCreateWithFlags(&ev4, cudaEventDisableTiming);
    }

    // init on stream 0; fork after it
    k_init<<<25, 128>>>(Wq, Wk, Wv, Wr);
    cudaEventRecord(ev0, 0);
    cudaStreamWaitEvent(s1, ev0, 0);
    cudaStreamWaitEvent(s3, ev0, 0);

    // Fourier pipeline, half A (batches 0-1, imgs 0-31) on stream 0
    k_projk<<<256, 128>>>(x_in, 0);
    k_fwdW<<<32 * 32, 288>>>(0);
    k_fwdH<<<32 * 17, 128>>>(0);
    k_pwf<<<65, 256>>>(al_pw, ah_pw, ph_pw, ph_s, 0);
    k_dwf<<<(32 * FSZ) / 256, 256>>>(al_dw, ah_dw, 0);
    k_invH<<<32 * 17, 128>>>(0);
    k_invW<<<32 * 64, 128>>>(0);

    // Fourier pipeline, half B (batches 2-3, imgs 32-63) on stream 3
    k_projk<<<256, 128, 0, s3>>>(x_in, 256);
    k_fwdW<<<32 * 32, 288, 0, s3>>>(32);
    k_fwdH<<<32 * 17, 128, 0, s3>>>(32);
    k_pwf<<<65, 256, 0, s3>>>(al_pw, ah_pw, ph_pw, ph_s, 2);
    k_dwf<<<(32 * FSZ) / 256, 256, 0, s3>>>(al_dw, ah_dw, 32);
    k_invH<<<32 * 17, 128, 0, s3>>>(32);
    k_invW<<<32 * 64, 128, 0, s3>>>(32);
    cudaEventRecord(ev4, s3);

    // side path (s1): q+v projection, then wavelet chain; spatial forks to s2
    k_projqv<<<512, 128, 0, s1>>>(x_in);
    cudaEventRecord(ev3, s1);
    cudaStreamWaitEvent(s2, ev3, 0);
    k_spatial<<<BB * 64, 256, 0, s2>>>(qs_dw, qs_pw, qs_g);
    cudaEventRecord(ev2, s2);

    k_haar<<<(BB * 64 * HWH) / 256, 256, 0, s1>>>();
    k_win<<<(BB * HWH) / 32, 256, 0, s1>>>(mlp_in, bng, bnb);
    k_wdw<<<(BB * 96 * HWH) / 256, 256, 0, s1>>>(mlp_dw);
    k_wout<<<BB * 64, 256, 0, s1>>>(mlp_out, res_s);
    cudaEventRecord(ev1, s1);

    // join: gram needs qm (spatial) + km (both Fourier halves)
    cudaStreamWaitEvent(0, ev2, 0);
    cudaStreamWaitEvent(0, ev4, 0);
    {
        dim3 g(64, BB);
        k_gram<<<g, 256>>>();
    }
    {
        dim3 g(8, BB);
        k_attn<<<g, 256>>>(We, Wproj, rescale);
    }
    // join wavelet (final needs vm)
    cudaStreamWaitEvent(0, ev1, 0);
    k_final<<<512, 128>>>(bproj, out);
}